// round 15
// baseline (speedup 1.0000x reference)
#include <cuda_runtime.h>
#include <cuda_fp16.h>
#include <cstdint>
#include <math.h>

// Problem dims
#define BS   128
#define SLEN 256
#define EDIM 512
#define HDIM 1024
#define VDIM 32000
#define ROWS (BS * SLEN)        // 32768
#define KEO  (2 * HDIM)         // 2048
#define KX   (EDIM + 2 * HDIM)  // 2560
#define KCAT (3 * HDIM + EDIM)  // 3584
#define NG   (4 * HDIM)         // 4096

// SIMT GEMM tile config (h_proj split-K)
#define TBM 128
#define TBN 64
#define TBK 16
#define NTHREADS 256
#define HP_SPLITS 8
#define GT_SPLITS 4

// mma.sync tile: CTA 256 thr, tile 128(M) x 256(N), k-step 32
#define PADROW 80               // bytes per 32-half row - conflict-free ldmatrix
#define SM_A1  10240            // B offset (A region is 10240 bytes)
#define STAGE1 30720            // stage: A 10240 + B 20480
#define DSMEM1 (3 * STAGE1)     // 92160 (attn, gates, fc; 3-stage)

// ---------------- scratch (device globals; no allocation allowed) ------------
__device__ float g_hproj_p[HP_SPLITS][BS * HDIM];
__device__ float g_score[ROWS];
__device__ float g_attn[BS * SLEN];
__device__ float g_x[BS * KX];
__device__ float g_cat[BS * KCAT];
__device__ float g_gatesp[GT_SPLITS][BS * NG];
__device__ __align__(16) __half g_eo_hi[(size_t)ROWS * KEO];
__device__ __align__(16) __half g_w_hi[(size_t)HDIM * KEO];
__device__ __align__(16) __half g_cat_hi[(size_t)BS * KCAT];
__device__ __align__(16) __half g_xh_hi[(size_t)BS * KCAT];
__device__ __align__(16) __half g_wg_hi[(size_t)NG * KCAT];

// ---------------- PTX helpers ------------------------------------------------
__device__ __forceinline__ uint32_t smem_u32(const void* p) {
    uint32_t a;
    asm("{ .reg .u64 t; cvta.to.shared.u64 t, %1; cvt.u32.u64 %0, t; }"
        : "=r"(a) : "l"(p));
    return a;
}

__device__ __forceinline__ void cp16(uint32_t dst, const void* src) {
    asm volatile("cp.async.cg.shared.global [%0], [%1], 16;"
                 :: "r"(dst), "l"(src) : "memory");
}
#define CP_COMMIT() asm volatile("cp.async.commit_group;" ::: "memory")
#define CP_WAIT(n)  asm volatile("cp.async.wait_group %0;" :: "n"(n) : "memory")

__device__ __forceinline__ void ldmx4(uint32_t* r, uint32_t addr) {
    asm volatile("ldmatrix.sync.aligned.m8n8.x4.shared.b16 {%0,%1,%2,%3}, [%4];"
                 : "=r"(r[0]), "=r"(r[1]), "=r"(r[2]), "=r"(r[3]) : "r"(addr));
}

__device__ __forceinline__ void sts128(uint32_t addr, uint32_t a, uint32_t b,
                                       uint32_t c, uint32_t d) {
    asm volatile("st.shared.v4.b32 [%0], {%1,%2,%3,%4};"
                 :: "r"(addr), "r"(a), "r"(b), "r"(c), "r"(d) : "memory");
}

__device__ __forceinline__ uint32_t h2u(__half2 h) {
    return *reinterpret_cast<uint32_t*>(&h);
}

// fp32-accumulate mma
__device__ __forceinline__ void mma16816(float* d, const uint32_t* a,
                                         const uint32_t* b) {
    asm volatile(
        "mma.sync.aligned.m16n8k16.row.col.f32.f16.f16.f32 "
        "{%0,%1,%2,%3}, {%4,%5,%6,%7}, {%8,%9}, {%0,%1,%2,%3};"
        : "+f"(d[0]), "+f"(d[1]), "+f"(d[2]), "+f"(d[3])
        : "r"(a[0]), "r"(a[1]), "r"(a[2]), "r"(a[3]), "r"(b[0]), "r"(b[1]));
}

// fp16-accumulate mma (potential 2x rate)
__device__ __forceinline__ void mma16816h(uint32_t* d, const uint32_t* a,
                                          const uint32_t* b) {
    asm volatile(
        "mma.sync.aligned.m16n8k16.row.col.f16.f16.f16.f16 "
        "{%0,%1}, {%2,%3,%4,%5}, {%6,%7}, {%0,%1};"
        : "+r"(d[0]), "+r"(d[1])
        : "r"(a[0]), "r"(a[1]), "r"(a[2]), "r"(a[3]), "r"(b[0]), "r"(b[1]));
}

__device__ __forceinline__ float ftanh(float x) {
    float e = __expf(2.f * x);
    return 1.f - 2.f / (e + 1.f);
}

// ---------------- 1-term fp16 mma machinery ----------------------------------
__device__ __forceinline__ void stage_load1(
    uint32_t sbase,
    const __half* __restrict__ Ah, int lda,
    const __half* __restrict__ Bh, int ldb, int tid, int kof)
{
#pragma unroll
    for (int i = 0; i < 2; ++i) {           // A: 128 rows x 32 k
        int idx = tid + 256 * i;
        int r = idx >> 2, c = idx & 3;
        uint32_t d = sbase + r * PADROW + c * 16;
        size_t go = (size_t)r * lda + kof + c * 8;
        cp16(d, Ah + go);
    }
#pragma unroll
    for (int i = 0; i < 4; ++i) {           // B: 256 rows x 32 k
        int idx = tid + 256 * i;
        int r = idx >> 2, c = idx & 3;
        uint32_t d = sbase + SM_A1 + r * PADROW + c * 16;
        size_t go = (size_t)r * ldb + kof + c * 8;
        cp16(d, Bh + go);
    }
}

// fp32-acc compute stage (gates, fc)
__device__ __forceinline__ void stage_compute1(uint32_t sbase, int lane,
                                               int wm, int wn,
                                               float (&acc)[4][8][4])
{
    const uint32_t a_row = wm * 64 + (lane & 7) + ((lane >> 3) & 1) * 8;
    const uint32_t a_colb = (lane >> 4) * 16;
    const uint32_t b_row = wn * 64 + (lane & 7) + ((lane >> 4) & 1) * 8;
    const uint32_t b_colb = ((lane >> 3) & 1) * 16;
#pragma unroll
    for (int kk = 0; kk < 2; ++kk) {
        uint32_t ahi[4][4], bfr[4][4];
        const uint32_t ka = sbase + a_row * PADROW + a_colb + kk * 32;
#pragma unroll
        for (int mt = 0; mt < 4; ++mt)
            ldmx4(ahi[mt], ka + mt * 16 * PADROW);
        const uint32_t kb = sbase + SM_A1 + b_row * PADROW + b_colb + kk * 32;
#pragma unroll
        for (int np = 0; np < 4; ++np) ldmx4(bfr[np], kb + np * 16 * PADROW);
#pragma unroll
        for (int mt = 0; mt < 4; ++mt)
#pragma unroll
            for (int np = 0; np < 4; ++np) {
                mma16816(acc[mt][np * 2],     ahi[mt], &bfr[np][0]);
                mma16816(acc[mt][np * 2 + 1], ahi[mt], &bfr[np][2]);
            }
    }
}

// fp16-acc compute stage (attn)
__device__ __forceinline__ void stage_compute1h(uint32_t sbase, int lane,
                                                int wm, int wn,
                                                uint32_t (&fac)[4][8][2])
{
    const uint32_t a_row = wm * 64 + (lane & 7) + ((lane >> 3) & 1) * 8;
    const uint32_t a_colb = (lane >> 4) * 16;
    const uint32_t b_row = wn * 64 + (lane & 7) + ((lane >> 4) & 1) * 8;
    const uint32_t b_colb = ((lane >> 3) & 1) * 16;
#pragma unroll
    for (int kk = 0; kk < 2; ++kk) {
        uint32_t ahi[4][4], bfr[4][4];
        const uint32_t ka = sbase + a_row * PADROW + a_colb + kk * 32;
#pragma unroll
        for (int mt = 0; mt < 4; ++mt)
            ldmx4(ahi[mt], ka + mt * 16 * PADROW);
        const uint32_t kb = sbase + SM_A1 + b_row * PADROW + b_colb + kk * 32;
#pragma unroll
        for (int np = 0; np < 4; ++np) ldmx4(bfr[np], kb + np * 16 * PADROW);
#pragma unroll
        for (int mt = 0; mt < 4; ++mt)
#pragma unroll
            for (int np = 0; np < 4; ++np) {
                mma16816h(fac[mt][np * 2],     ahi[mt], &bfr[np][0]);
                mma16816h(fac[mt][np * 2 + 1], ahi[mt], &bfr[np][2]);
            }
    }
}

__device__ __forceinline__ void drain_fac(uint32_t (&fac)[4][8][2],
                                          float (&acc)[4][8][4]) {
#pragma unroll
    for (int mt = 0; mt < 4; ++mt)
#pragma unroll
        for (int nt = 0; nt < 8; ++nt) {
            float2 t0 = __half22float2(*(__half2*)&fac[mt][nt][0]);
            float2 t1 = __half22float2(*(__half2*)&fac[mt][nt][1]);
            acc[mt][nt][0] += t0.x;
            acc[mt][nt][1] += t0.y;
            acc[mt][nt][2] += t1.x;
            acc[mt][nt][3] += t1.y;
            fac[mt][nt][0] = 0;
            fac[mt][nt][1] = 0;
        }
}

// 3-stage pipelined mainloop, k-step 32, fp32 acc (gates, fc path reuses parts)
__device__ __forceinline__ void gemm_mainloop1(
    const __half* Ah, int lda, const __half* Bh, int ldb,
    int KT, uint32_t sm0, int tid, float (&acc)[4][8][4])
{
    const int lane = tid & 31, wid = tid >> 5;
    const int wm = wid >> 2, wn = wid & 3;
    stage_load1(sm0, Ah, lda, Bh, ldb, tid, 0);
    CP_COMMIT();
    stage_load1(sm0 + STAGE1, Ah, lda, Bh, ldb, tid, 32);
    CP_COMMIT();
    int sl = 2, sc = 0;
    for (int it = 0; it < KT; ++it) {
        CP_WAIT(1);
        __syncthreads();
        if (it + 2 < KT)
            stage_load1(sm0 + sl * STAGE1, Ah, lda, Bh, ldb, tid, (it + 2) * 32);
        CP_COMMIT();
        stage_compute1(sm0 + sc * STAGE1, lane, wm, wn, acc);
        if (++sl == 3) sl = 0;
        if (++sc == 3) sc = 0;
    }
}

// 3-stage mainloop with fp16 accumulation, drain to fp32 every 4 iters (attn)
__device__ __forceinline__ void gemm_mainloop1h(
    const __half* Ah, int lda, const __half* Bh, int ldb,
    int KT, uint32_t sm0, int tid, float (&acc)[4][8][4])
{
    const int lane = tid & 31, wid = tid >> 5;
    const int wm = wid >> 2, wn = wid & 3;
    uint32_t fac[4][8][2];
#pragma unroll
    for (int mt = 0; mt < 4; ++mt)
#pragma unroll
        for (int nt = 0; nt < 8; ++nt)
            fac[mt][nt][0] = fac[mt][nt][1] = 0;

    stage_load1(sm0, Ah, lda, Bh, ldb, tid, 0);
    CP_COMMIT();
    stage_load1(sm0 + STAGE1, Ah, lda, Bh, ldb, tid, 32);
    CP_COMMIT();
    int sl = 2, sc = 0;
    for (int it = 0; it < KT; ++it) {
        CP_WAIT(1);
        __syncthreads();
        if (it + 2 < KT)
            stage_load1(sm0 + sl * STAGE1, Ah, lda, Bh, ldb, tid, (it + 2) * 32);
        CP_COMMIT();
        stage_compute1h(sm0 + sc * STAGE1, lane, wm, wn, fac);
        if ((it & 3) == 3) drain_fac(fac, acc);
        if (++sl == 3) sl = 0;
        if (++sc == 3) sc = 0;
    }
    if (KT & 3) drain_fac(fac, acc);
}

// ---------------- conversions -------------------------------------------------
__global__ void conv_hi(const float4* __restrict__ src,
                        __half2* __restrict__ hi) {
    size_t i = (size_t)blockIdx.x * blockDim.x + threadIdx.x;
    float4 v = src[i];
    hi[i * 2 + 0] = __floats2half2_rn(v.x, v.y);
    hi[i * 2 + 1] = __floats2half2_rn(v.z, v.w);
}

// gather attn_w[:, H:3H] -> g_w_hi [HDIM x KEO]
__global__ void conv_w_kernel(const float* __restrict__ attn_w) {
    int n = blockIdx.x;
    const float2* src = (const float2*)(attn_w + (size_t)n * 3 * HDIM + HDIM);
    __half2* hi = (__half2*)(g_w_hi + (size_t)n * KEO);
    for (int c = threadIdx.x; c < KEO / 2; c += blockDim.x) {
        float2 v = src[c];
        hi[c] = __floats2half2_rn(v.x, v.y);
    }
}

// [w_ih | w_hh] rows -> g_wg_hi [NG x KCAT]
__global__ void conv_wg_kernel(const float* __restrict__ w_ih,
                               const float* __restrict__ w_hh) {
    int n = blockIdx.x;
    for (int k = threadIdx.x; k < KCAT; k += blockDim.x) {
        float v = (k < KX) ? w_ih[(size_t)n * KX + k]
                           : w_hh[(size_t)n * HDIM + (k - KX)];
        g_wg_hi[(size_t)n * KCAT + k] = __float2half_rn(v);
    }
}

// [x | h0] rows -> g_xh_hi [BS x KCAT]
__global__ void conv_xh_kernel(const float* __restrict__ h0) {
    int b = blockIdx.x;
    for (int k = threadIdx.x; k < KCAT; k += blockDim.x) {
        float v = (k < KX) ? g_x[(size_t)b * KX + k]
                           : h0[(size_t)b * HDIM + (k - KX)];
        g_xh_hi[(size_t)b * KCAT + k] = __float2half_rn(v);
    }
}

// ---------------- embedding gather ------------------------------------------
__global__ void embed_kernel(const int* __restrict__ tok,
                             const float* __restrict__ emb_w) {
    int b = blockIdx.x;
    int t = tok[b];
    for (int e = threadIdx.x; e < EDIM; e += blockDim.x) {
        float v = emb_w[(size_t)t * EDIM + e];
        g_x[(size_t)b * KX + e] = v;
        g_cat[(size_t)b * KCAT + 3 * HDIM + e] = v;
    }
}

// ---------------- h_proj split-K SIMT GEMM -----------------------------------
__global__ __launch_bounds__(NTHREADS)
void hproj_splitk(const float* __restrict__ A, const float* __restrict__ B) {
    __shared__ float As[TBK][TBM];
    __shared__ float Bs[TBK][TBN];
    const int tid = threadIdx.x;
    const int col0 = blockIdx.x * TBN;
    const int k0base = blockIdx.y * (HDIM / HP_SPLITS);
    const int tm0 = (tid >> 4) * 8;
    const int tn0 = (tid & 15) * 4;
    float acc[8][4] = {};
    for (int kk = 0; kk < HDIM / HP_SPLITS; kk += TBK) {
        const int k0 = k0base + kk;
#pragma unroll
        for (int t = 0; t < 2; ++t) {
            int lin = (tid + t * NTHREADS) * 4;
            int r = lin >> 4, cc = lin & 15;
            float4 v = *(const float4*)(A + (size_t)r * HDIM + k0 + cc);
            As[cc + 0][r] = v.x; As[cc + 1][r] = v.y;
            As[cc + 2][r] = v.z; As[cc + 3][r] = v.w;
        }
        {
            int lin = tid * 4;
            int r = lin >> 4, cc = lin & 15;
            float4 v = *(const float4*)(B + (size_t)(col0 + r) * 3 * HDIM + k0 + cc);
            Bs[cc + 0][r] = v.x; Bs[cc + 1][r] = v.y;
            Bs[cc + 2][r] = v.z; Bs[cc + 3][r] = v.w;
        }
        __syncthreads();
#pragma unroll
        for (int k = 0; k < TBK; ++k) {
            float4 a0 = *(const float4*)&As[k][tm0];
            float4 a1 = *(const float4*)&As[k][tm0 + 4];
            float4 b0 = *(const float4*)&Bs[k][tn0];
            float a[8] = {a0.x, a0.y, a0.z, a0.w, a1.x, a1.y, a1.z, a1.w};
            float b[4] = {b0.x, b0.y, b0.z, b0.w};
#pragma unroll
            for (int i = 0; i < 8; ++i)
#pragma unroll
                for (int j = 0; j < 4; ++j)
                    acc[i][j] = fmaf(a[i], b[j], acc[i][j]);
        }
        __syncthreads();
    }
    float* outp = g_hproj_p[blockIdx.y];
#pragma unroll
    for (int i = 0; i < 8; ++i)
#pragma unroll
        for (int j = 0; j < 4; ++j)
            outp[(size_t)(tm0 + i) * HDIM + col0 + tn0 + j] = acc[i][j];
}

// ================= attention energy: fp16-acc mma + fused epilogue ===========
__global__ __launch_bounds__(256, 1)
void attn_mma(const float* __restrict__ attn_b, const float* __restrict__ v_w) {
    extern __shared__ char dsm[];
    __shared__ float base_sh[256], v_sh[256], red[4][128];
    const uint32_t sm0 = smem_u32(dsm);
    const int tid = threadIdx.x, lane = tid & 31, wid = tid >> 5;
    const int wm = wid >> 2, wn = wid & 3;
    const int row0 = blockIdx.x * 128;
    const int b_idx = row0 >> 8;

    float rowpart[4][2] = {};
    for (int ch = 0; ch < 4; ++ch) {
        const int n0 = ch * 256;
        __syncthreads();
        {
            float s = attn_b[n0 + tid];
#pragma unroll
            for (int p = 0; p < HP_SPLITS; ++p)
                s += g_hproj_p[p][(size_t)b_idx * HDIM + n0 + tid];
            base_sh[tid] = s;
        }
        v_sh[tid] = v_w[n0 + tid];
        float acc[4][8][4] = {};
        gemm_mainloop1h(g_eo_hi + (size_t)row0 * KEO, KEO,
                        g_w_hi + (size_t)n0 * KEO, KEO,
                        64, sm0, tid, acc);
#pragma unroll
        for (int mt = 0; mt < 4; ++mt)
#pragma unroll
            for (int nt = 0; nt < 8; ++nt) {
                int nb = wn * 64 + nt * 8 + (lane & 3) * 2;
                float b0 = base_sh[nb], b1 = base_sh[nb + 1];
                float v0 = v_sh[nb], v1 = v_sh[nb + 1];
                rowpart[mt][0] += v0 * ftanh(acc[mt][nt][0] + b0)
                                + v1 * ftanh(acc[mt][nt][1] + b1);
                rowpart[mt][1] += v0 * ftanh(acc[mt][nt][2] + b0)
                                + v1 * ftanh(acc[mt][nt][3] + b1);
            }
    }
#pragma unroll
    for (int mt = 0; mt < 4; ++mt)
#pragma unroll
        for (int h = 0; h < 2; ++h) {
            float v = rowpart[mt][h];
            v += __shfl_xor_sync(0xffffffff, v, 1);
            v += __shfl_xor_sync(0xffffffff, v, 2);
            if ((lane & 3) == 0)
                red[wn][wm * 64 + mt * 16 + (lane >> 2) + 8 * h] = v;
        }
    __syncthreads();
    if (tid < 128)
        g_score[row0 + tid] = red[0][tid] + red[1][tid] + red[2][tid] + red[3][tid];
}

// ================= fc: 1-term, B (fco_w) fp32->fp16 in-kernel, 3-stage =======
__device__ __forceinline__ void ldg_fcB(const float* __restrict__ fco,
                                        int n0, int kof, int tid, float4* r) {
    const float4* src = (const float4*)(fco + (size_t)(n0 + tid) * KCAT + kof);
#pragma unroll
    for (int j = 0; j < 8; ++j) r[j] = src[j];
}

__device__ __forceinline__ void sts_fcB(uint32_t sbase, int tid,
                                        const float4* r) {
    uint32_t bh = sbase + SM_A1 + tid * PADROW;
#pragma unroll
    for (int j = 0; j < 8; j += 2) {
        __half2 h0 = __floats2half2_rn(r[j].x,     r[j].y);
        __half2 h1 = __floats2half2_rn(r[j].z,     r[j].w);
        __half2 h2 = __floats2half2_rn(r[j + 1].x, r[j + 1].y);
        __half2 h3 = __floats2half2_rn(r[j + 1].z, r[j + 1].w);
        sts128(bh + j * 8, h2u(h0), h2u(h1), h2u(h2), h2u(h3));
    }
}

__device__ __forceinline__ void cp_fcA(uint32_t sbase, int kof, int tid) {
#pragma unroll
    for (int i = 0; i < 2; ++i) {
        int idx = tid + 256 * i;
        int r = idx >> 2, c = idx & 3;
        uint32_t d = sbase + r * PADROW + c * 16;
        size_t go = (size_t)r * KCAT + kof + c * 8;
        cp16(d, g_cat_hi + go);
    }
}

__global__ __launch_bounds__(256, 1)
void fc_mma(const float* __restrict__ fco_w, const float* __restrict__ fco_b,
            float* __restrict__ out) {
    extern __shared__ char dsm[];
    const uint32_t sm0 = smem_u32(dsm);
    const int tid = threadIdx.x, lane = tid & 31, wid = tid >> 5;
    const int wm = wid >> 2, wn = wid & 3;
    const int n0 = blockIdx.x * 256;
    const int KT = KCAT / 32;   // 112
    float acc[4][8][4] = {};
    float4 br[8];

    ldg_fcB(fco_w, n0, 0, tid, br);
    sts_fcB(sm0, tid, br);
    cp_fcA(sm0, 0, tid);
    CP_COMMIT();
    ldg_fcB(fco_w, n0, 32, tid, br);
    sts_fcB(sm0 + STAGE1, tid, br);
    cp_fcA(sm0 + STAGE1, 32, tid);
    CP_COMMIT();
    ldg_fcB(fco_w, n0, 64, tid, br);

    for (int it = 0; it < KT; ++it) {
        CP_WAIT(1);
        __syncthreads();
        const int s2 = (it + 2) % 3;
        if (it + 2 < KT) {
            sts_fcB(sm0 + s2 * STAGE1, tid, br);
            cp_fcA(sm0 + s2 * STAGE1, (it + 2) * 32, tid);
        }
        CP_COMMIT();
        if (it + 3 < KT) ldg_fcB(fco_w, n0, (it + 3) * 32, tid, br);
        stage_compute1(sm0 + (it % 3) * STAGE1, lane, wm, wn, acc);
    }
#pragma unroll
    for (int mt = 0; mt < 4; ++mt) {
        int r0 = wm * 64 + mt * 16 + (lane >> 2);
#pragma unroll
        for (int nt = 0; nt < 8; ++nt) {
            int n = n0 + wn * 64 + nt * 8 + (lane & 3) * 2;
            float b0 = fco_b[n], b1 = fco_b[n + 1];
            out[(size_t)r0 * VDIM + n] = acc[mt][nt][0] + b0;
            out[(size_t)r0 * VDIM + n + 1] = acc[mt][nt][1] + b1;
            out[(size_t)(r0 + 8) * VDIM + n] = acc[mt][nt][2] + b0;
            out[(size_t)(r0 + 8) * VDIM + n + 1] = acc[mt][nt][3] + b1;
        }
    }
}

// ================= gates: [x|h] @ [w_ih|w_hh]^T, split-K=4, 1-term ===========
__global__ __launch_bounds__(256, 1)
void gates_mma() {
    extern __shared__ char dsm[];
    const uint32_t sm0 = smem_u32(dsm);
    const int tid = threadIdx.x, lane = tid & 31, wid = tid >> 5;
    const int wm = wid >> 2, wn = wid & 3;
    const int n0 = (blockIdx.x & 15) * 256;
    const int ks = blockIdx.x >> 4;
    const int kof = ks * (KCAT / GT_SPLITS);
    float acc[4][8][4] = {};
    gemm_mainloop1(g_xh_hi + kof, KCAT,
                   g_wg_hi + (size_t)n0 * KCAT + kof, KCAT,
                   KCAT / GT_SPLITS / 32, sm0, tid, acc);
    float* gp = g_gatesp[ks];
#pragma unroll
    for (int mt = 0; mt < 4; ++mt) {
        int r0 = wm * 64 + mt * 16 + (lane >> 2);
#pragma unroll
        for (int nt = 0; nt < 8; ++nt) {
            int n = n0 + wn * 64 + nt * 8 + (lane & 3) * 2;
            gp[(size_t)r0 * NG + n] = acc[mt][nt][0];
            gp[(size_t)r0 * NG + n + 1] = acc[mt][nt][1];
            gp[(size_t)(r0 + 8) * NG + n] = acc[mt][nt][2];
            gp[(size_t)(r0 + 8) * NG + n + 1] = acc[mt][nt][3];
        }
    }
}

// ---------------- softmax over seq -------------------------------------------
__global__ void softmax_kernel() {
    __shared__ float sred[SLEN];
    int b = blockIdx.x, s = threadIdx.x;
    float sc = g_score[b * SLEN + s];
    sred[s] = sc; __syncthreads();
    for (int o = SLEN / 2; o > 0; o >>= 1) {
        if (s < o) sred[s] = fmaxf(sred[s], sred[s + o]);
        __syncthreads();
    }
    float m = sred[0]; __syncthreads();
    float e = expf(sc - m);
    sred[s] = e; __syncthreads();
    for (int o = SLEN / 2; o > 0; o >>= 1) {
        if (s < o) sred[s] += sred[s + o];
        __syncthreads();
    }
    g_attn[b * SLEN + s] = e / sred[0];
}

// ---------------- weighted = a @ eo (fp16 eo_hi, 4 cols/thread) --------------
__global__ void weighted_kernel() {
    __shared__ float a_sh[SLEN];
    int b = blockIdx.y;
    int d0 = (blockIdx.x * 256 + threadIdx.x) * 4;
    if (threadIdx.x < SLEN) a_sh[threadIdx.x] = g_attn[b * SLEN + threadIdx.x];
    __syncthreads();
    const __half* eob = g_eo_hi + (size_t)b * SLEN * KEO + d0;
    float acc0 = 0.f, acc1 = 0.f, acc2 = 0.f, acc3 = 0.f;
#pragma unroll 4
    for (int s = 0; s < SLEN; ++s) {
        uint2 u = *(const uint2*)(eob + (size_t)s * KEO);
        float2 p0 = __half22float2(*(__half2*)&u.x);
        float2 p1 = __half22float2(*(__half2*)&u.y);
        float a = a_sh[s];
        acc0 = fmaf(a, p0.x, acc0);
        acc1 = fmaf(a, p0.y, acc1);
        acc2 = fmaf(a, p1.x, acc2);
        acc3 = fmaf(a, p1.y, acc3);
    }
    float* gx = g_x + (size_t)b * KX + EDIM + d0;
    float* gc = g_cat + (size_t)b * KCAT + HDIM + d0;
    gx[0] = acc0; gx[1] = acc1; gx[2] = acc2; gx[3] = acc3;
    gc[0] = acc0; gc[1] = acc1; gc[2] = acc2; gc[3] = acc3;
}

// ---------------- LSTM cell elementwise --------------------------------------
__global__ void lstm_kernel(const float* __restrict__ c0,
                            const float* __restrict__ b_ih,
                            const float* __restrict__ b_hh,
                            float* __restrict__ out) {
    int idx = blockIdx.x * blockDim.x + threadIdx.x;   // [0, 128*1024)
    int b = idx >> 10, h = idx & 1023;
    float gs[4];
#pragma unroll
    for (int g = 0; g < 4; ++g) {
        float s = b_ih[g * HDIM + h] + b_hh[g * HDIM + h];
#pragma unroll
        for (int p = 0; p < GT_SPLITS; ++p)
            s += g_gatesp[p][(size_t)b * NG + g * HDIM + h];
        gs[g] = s;
    }
    float si = 1.f / (1.f + expf(-gs[0]));
    float sf = 1.f / (1.f + expf(-gs[1]));
    float so = 1.f / (1.f + expf(-gs[3]));
    float cn = sf * c0[idx] + si * tanhf(gs[2]);
    float hn = so * tanhf(cn);
    g_cat[(size_t)b * KCAT + h] = hn;
    out[(size_t)BS * VDIM + idx] = hn;                  // h_new
    out[(size_t)BS * VDIM + BS * HDIM + idx] = cn;      // c_new
}

// ---------------- launch -----------------------------------------------------
extern "C" void kernel_launch(void* const* d_in, const int* in_sizes, int n_in,
                              void* d_out, int out_size) {
    const int*   inp_tok = (const int*)  d_in[0];
    const float* h0      = (const float*)d_in[1];
    const float* c0      = (const float*)d_in[2];
    const float* eo      = (const float*)d_in[3];
    const float* emb_w   = (const float*)d_in[4];
    const float* attn_w  = (const float*)d_in[5];
    const float* attn_b  = (const float*)d_in[6];
    const float* v_w     = (const float*)d_in[7];
    const float* w_ih    = (const float*)d_in[8];
    const float* w_hh    = (const float*)d_in[9];
    const float* b_ih    = (const float*)d_in[10];
    const float* b_hh    = (const float*)d_in[11];
    const float* fco_w   = (const float*)d_in[12];
    const float* fco_b   = (const float*)d_in[13];
    float* out = (float*)d_out;

    void *p_eo_hi, *p_cat, *p_cat_hi;
    cudaGetSymbolAddress(&p_eo_hi,  g_eo_hi);
    cudaGetSymbolAddress(&p_cat,    g_cat);
    cudaGetSymbolAddress(&p_cat_hi, g_cat_hi);

    cudaFuncSetAttribute(attn_mma,  cudaFuncAttributeMaxDynamicSharedMemorySize, DSMEM1);
    cudaFuncSetAttribute(gates_mma, cudaFuncAttributeMaxDynamicSharedMemorySize, DSMEM1);
    cudaFuncSetAttribute(fc_mma,    cudaFuncAttributeMaxDynamicSharedMemorySize, DSMEM1);

    // conversions
    conv_hi<<<(ROWS * (size_t)KEO) / 4 / 256, 256>>>(
        (const float4*)eo, (__half2*)p_eo_hi);
    conv_w_kernel<<<HDIM, 256>>>(attn_w);
    conv_wg_kernel<<<NG, 256>>>(w_ih, w_hh);

    // embedding + h_proj (split-K x8)
    embed_kernel<<<BS, 256>>>(inp_tok, emb_w);
    hproj_splitk<<<dim3(HDIM / TBN, HP_SPLITS), NTHREADS>>>(h0, attn_w);

    // attention scores (fp16-acc GEMM + tanh + v-dot; sums hproj planes)
    attn_mma<<<256, 256, DSMEM1>>>(attn_b, v_w);
    softmax_kernel<<<BS, SLEN>>>();
    weighted_kernel<<<dim3(KEO / 1024, BS), 256>>>();

    // LSTM gates (split-K x4, 1-term)
    conv_xh_kernel<<<BS, 256>>>(h0);
    gates_mma<<<16 * GT_SPLITS, 256, DSMEM1>>>();
    lstm_kernel<<<(BS * HDIM) / 256, 256>>>(c0, b_ih, b_hh, out);

    // output projection (in-kernel fco conversion, 1-term, 3-stage)
    conv_hi<<<((size_t)BS * KCAT) / 4 / 256, 256>>>(
        (const float4*)p_cat, (__half2*)p_cat_hi);
    fc_mma<<<VDIM / 256, 256, DSMEM1>>>(fco_w, fco_b, out);
}

// round 16
// speedup vs baseline: 1.0473x; 1.0473x over previous
#include <cuda_runtime.h>
#include <cuda_fp16.h>
#include <cstdint>
#include <math.h>

// Problem dims
#define BS   128
#define SLEN 256
#define EDIM 512
#define HDIM 1024
#define VDIM 32000
#define ROWS (BS * SLEN)        // 32768
#define KEO  (2 * HDIM)         // 2048
#define KX   (EDIM + 2 * HDIM)  // 2560
#define KCAT (3 * HDIM + EDIM)  // 3584
#define NG   (4 * HDIM)         // 4096

// SIMT GEMM tile config (h_proj split-K)
#define TBM 128
#define TBN 64
#define TBK 16
#define NTHREADS 256
#define HP_SPLITS 8
#define GT_SPLITS 8

// mma.sync tile: CTA 256 thr, tile 128(M) x 256(N), k-step 32
#define PADROW 80               // bytes per 32-half row - conflict-free ldmatrix
#define SM_A1  10240            // B offset (A region is 10240 bytes)
#define STAGE1 30720            // stage: A 10240 + B 20480
#define DSMEM1 (3 * STAGE1)     // 92160 (attn, gates, fc; 3-stage)

// ---------------- scratch (device globals; no allocation allowed) ------------
__device__ float g_hproj_p[HP_SPLITS][BS * HDIM];
__device__ float g_score[ROWS];
__device__ float g_attn[BS * SLEN];
__device__ float g_x[BS * KX];
__device__ float g_cat[BS * KCAT];
__device__ float g_gatesp[GT_SPLITS][BS * NG];
__device__ __align__(16) __half g_eo_hi[(size_t)ROWS * KEO];
__device__ __align__(16) __half g_w_hi[(size_t)HDIM * KEO];
__device__ __align__(16) __half g_cat_hi[(size_t)BS * KCAT];
__device__ __align__(16) __half g_xh_hi[(size_t)BS * KCAT];
__device__ __align__(16) __half g_wg_hi[(size_t)NG * KCAT];

// ---------------- PTX helpers ------------------------------------------------
__device__ __forceinline__ uint32_t smem_u32(const void* p) {
    uint32_t a;
    asm("{ .reg .u64 t; cvta.to.shared.u64 t, %1; cvt.u32.u64 %0, t; }"
        : "=r"(a) : "l"(p));
    return a;
}

__device__ __forceinline__ void cp16(uint32_t dst, const void* src) {
    asm volatile("cp.async.cg.shared.global [%0], [%1], 16;"
                 :: "r"(dst), "l"(src) : "memory");
}
#define CP_COMMIT() asm volatile("cp.async.commit_group;" ::: "memory")
#define CP_WAIT(n)  asm volatile("cp.async.wait_group %0;" :: "n"(n) : "memory")

__device__ __forceinline__ void ldmx4(uint32_t* r, uint32_t addr) {
    asm volatile("ldmatrix.sync.aligned.m8n8.x4.shared.b16 {%0,%1,%2,%3}, [%4];"
                 : "=r"(r[0]), "=r"(r[1]), "=r"(r[2]), "=r"(r[3]) : "r"(addr));
}

__device__ __forceinline__ void sts128(uint32_t addr, uint32_t a, uint32_t b,
                                       uint32_t c, uint32_t d) {
    asm volatile("st.shared.v4.b32 [%0], {%1,%2,%3,%4};"
                 :: "r"(addr), "r"(a), "r"(b), "r"(c), "r"(d) : "memory");
}

__device__ __forceinline__ uint32_t h2u(__half2 h) {
    return *reinterpret_cast<uint32_t*>(&h);
}

__device__ __forceinline__ void mma16816(float* d, const uint32_t* a,
                                         const uint32_t* b) {
    asm volatile(
        "mma.sync.aligned.m16n8k16.row.col.f32.f16.f16.f32 "
        "{%0,%1,%2,%3}, {%4,%5,%6,%7}, {%8,%9}, {%0,%1,%2,%3};"
        : "+f"(d[0]), "+f"(d[1]), "+f"(d[2]), "+f"(d[3])
        : "r"(a[0]), "r"(a[1]), "r"(a[2]), "r"(a[3]), "r"(b[0]), "r"(b[1]));
}

__device__ __forceinline__ float ftanh(float x) {
    float e = __expf(2.f * x);
    return 1.f - 2.f / (e + 1.f);
}

// ---------------- 1-term fp16 mma machinery ----------------------------------
__device__ __forceinline__ void stage_load1(
    uint32_t sbase,
    const __half* __restrict__ Ah, int lda,
    const __half* __restrict__ Bh, int ldb, int tid, int kof)
{
#pragma unroll
    for (int i = 0; i < 2; ++i) {           // A: 128 rows x 32 k
        int idx = tid + 256 * i;
        int r = idx >> 2, c = idx & 3;
        uint32_t d = sbase + r * PADROW + c * 16;
        size_t go = (size_t)r * lda + kof + c * 8;
        cp16(d, Ah + go);
    }
#pragma unroll
    for (int i = 0; i < 4; ++i) {           // B: 256 rows x 32 k
        int idx = tid + 256 * i;
        int r = idx >> 2, c = idx & 3;
        uint32_t d = sbase + SM_A1 + r * PADROW + c * 16;
        size_t go = (size_t)r * ldb + kof + c * 8;
        cp16(d, Bh + go);
    }
}

__device__ __forceinline__ void stage_compute1(uint32_t sbase, int lane,
                                               int wm, int wn,
                                               float (&acc)[4][8][4])
{
    const uint32_t a_row = wm * 64 + (lane & 7) + ((lane >> 3) & 1) * 8;
    const uint32_t a_colb = (lane >> 4) * 16;
    const uint32_t b_row = wn * 64 + (lane & 7) + ((lane >> 4) & 1) * 8;
    const uint32_t b_colb = ((lane >> 3) & 1) * 16;
#pragma unroll
    for (int kk = 0; kk < 2; ++kk) {
        uint32_t ahi[4][4], bfr[4][4];
        const uint32_t ka = sbase + a_row * PADROW + a_colb + kk * 32;
#pragma unroll
        for (int mt = 0; mt < 4; ++mt)
            ldmx4(ahi[mt], ka + mt * 16 * PADROW);
        const uint32_t kb = sbase + SM_A1 + b_row * PADROW + b_colb + kk * 32;
#pragma unroll
        for (int np = 0; np < 4; ++np) ldmx4(bfr[np], kb + np * 16 * PADROW);
#pragma unroll
        for (int mt = 0; mt < 4; ++mt)
#pragma unroll
            for (int np = 0; np < 4; ++np) {
                mma16816(acc[mt][np * 2],     ahi[mt], &bfr[np][0]);
                mma16816(acc[mt][np * 2 + 1], ahi[mt], &bfr[np][2]);
            }
    }
}

// 3-stage pipelined mainloop, k-step 32, 1-term fp32-acc
__device__ __forceinline__ void gemm_mainloop1(
    const __half* Ah, int lda, const __half* Bh, int ldb,
    int KT, uint32_t sm0, int tid, float (&acc)[4][8][4])
{
    const int lane = tid & 31, wid = tid >> 5;
    const int wm = wid >> 2, wn = wid & 3;
    stage_load1(sm0, Ah, lda, Bh, ldb, tid, 0);
    CP_COMMIT();
    stage_load1(sm0 + STAGE1, Ah, lda, Bh, ldb, tid, 32);
    CP_COMMIT();
    int sl = 2, sc = 0;
    for (int it = 0; it < KT; ++it) {
        CP_WAIT(1);
        __syncthreads();
        if (it + 2 < KT)
            stage_load1(sm0 + sl * STAGE1, Ah, lda, Bh, ldb, tid, (it + 2) * 32);
        CP_COMMIT();
        stage_compute1(sm0 + sc * STAGE1, lane, wm, wn, acc);
        if (++sl == 3) sl = 0;
        if (++sc == 3) sc = 0;
    }
}

// ---------------- conversions -------------------------------------------------
__global__ void conv_hi(const float4* __restrict__ src,
                        __half2* __restrict__ hi) {
    size_t i = (size_t)blockIdx.x * blockDim.x + threadIdx.x;
    float4 v = src[i];
    hi[i * 2 + 0] = __floats2half2_rn(v.x, v.y);
    hi[i * 2 + 1] = __floats2half2_rn(v.z, v.w);
}

// gather attn_w[:, H:3H] -> g_w_hi [HDIM x KEO]
__global__ void conv_w_kernel(const float* __restrict__ attn_w) {
    int n = blockIdx.x;
    const float2* src = (const float2*)(attn_w + (size_t)n * 3 * HDIM + HDIM);
    __half2* hi = (__half2*)(g_w_hi + (size_t)n * KEO);
    for (int c = threadIdx.x; c < KEO / 2; c += blockDim.x) {
        float2 v = src[c];
        hi[c] = __floats2half2_rn(v.x, v.y);
    }
}

// [w_ih | w_hh] rows -> g_wg_hi [NG x KCAT]
__global__ void conv_wg_kernel(const float* __restrict__ w_ih,
                               const float* __restrict__ w_hh) {
    int n = blockIdx.x;
    for (int k = threadIdx.x; k < KCAT; k += blockDim.x) {
        float v = (k < KX) ? w_ih[(size_t)n * KX + k]
                           : w_hh[(size_t)n * HDIM + (k - KX)];
        g_wg_hi[(size_t)n * KCAT + k] = __float2half_rn(v);
    }
}

// [x | h0] rows -> g_xh_hi [BS x KCAT]
__global__ void conv_xh_kernel(const float* __restrict__ h0) {
    int b = blockIdx.x;
    for (int k = threadIdx.x; k < KCAT; k += blockDim.x) {
        float v = (k < KX) ? g_x[(size_t)b * KX + k]
                           : h0[(size_t)b * HDIM + (k - KX)];
        g_xh_hi[(size_t)b * KCAT + k] = __float2half_rn(v);
    }
}

// ---------------- embedding gather ------------------------------------------
__global__ void embed_kernel(const int* __restrict__ tok,
                             const float* __restrict__ emb_w) {
    int b = blockIdx.x;
    int t = tok[b];
    for (int e = threadIdx.x; e < EDIM; e += blockDim.x) {
        float v = emb_w[(size_t)t * EDIM + e];
        g_x[(size_t)b * KX + e] = v;
        g_cat[(size_t)b * KCAT + 3 * HDIM + e] = v;
    }
}

// ---------------- h_proj split-K SIMT GEMM -----------------------------------
__global__ __launch_bounds__(NTHREADS)
void hproj_splitk(const float* __restrict__ A, const float* __restrict__ B) {
    __shared__ float As[TBK][TBM];
    __shared__ float Bs[TBK][TBN];
    const int tid = threadIdx.x;
    const int col0 = blockIdx.x * TBN;
    const int k0base = blockIdx.y * (HDIM / HP_SPLITS);
    const int tm0 = (tid >> 4) * 8;
    const int tn0 = (tid & 15) * 4;
    float acc[8][4] = {};
    for (int kk = 0; kk < HDIM / HP_SPLITS; kk += TBK) {
        const int k0 = k0base + kk;
#pragma unroll
        for (int t = 0; t < 2; ++t) {
            int lin = (tid + t * NTHREADS) * 4;
            int r = lin >> 4, cc = lin & 15;
            float4 v = *(const float4*)(A + (size_t)r * HDIM + k0 + cc);
            As[cc + 0][r] = v.x; As[cc + 1][r] = v.y;
            As[cc + 2][r] = v.z; As[cc + 3][r] = v.w;
        }
        {
            int lin = tid * 4;
            int r = lin >> 4, cc = lin & 15;
            float4 v = *(const float4*)(B + (size_t)(col0 + r) * 3 * HDIM + k0 + cc);
            Bs[cc + 0][r] = v.x; Bs[cc + 1][r] = v.y;
            Bs[cc + 2][r] = v.z; Bs[cc + 3][r] = v.w;
        }
        __syncthreads();
#pragma unroll
        for (int k = 0; k < TBK; ++k) {
            float4 a0 = *(const float4*)&As[k][tm0];
            float4 a1 = *(const float4*)&As[k][tm0 + 4];
            float4 b0 = *(const float4*)&Bs[k][tn0];
            float a[8] = {a0.x, a0.y, a0.z, a0.w, a1.x, a1.y, a1.z, a1.w};
            float b[4] = {b0.x, b0.y, b0.z, b0.w};
#pragma unroll
            for (int i = 0; i < 8; ++i)
#pragma unroll
                for (int j = 0; j < 4; ++j)
                    acc[i][j] = fmaf(a[i], b[j], acc[i][j]);
        }
        __syncthreads();
    }
    float* outp = g_hproj_p[blockIdx.y];
#pragma unroll
    for (int i = 0; i < 8; ++i)
#pragma unroll
        for (int j = 0; j < 4; ++j)
            outp[(size_t)(tm0 + i) * HDIM + col0 + tn0 + j] = acc[i][j];
}

// ================= attention energy: 1-term fp16 mma + fused epilogue ========
__global__ __launch_bounds__(256, 1)
void attn_mma(const float* __restrict__ attn_b, const float* __restrict__ v_w) {
    extern __shared__ char dsm[];
    __shared__ float base_sh[256], v_sh[256], red[4][128];
    const uint32_t sm0 = smem_u32(dsm);
    const int tid = threadIdx.x, lane = tid & 31, wid = tid >> 5;
    const int wm = wid >> 2, wn = wid & 3;
    const int row0 = blockIdx.x * 128;
    const int b_idx = row0 >> 8;

    float rowpart[4][2] = {};
    for (int ch = 0; ch < 4; ++ch) {
        const int n0 = ch * 256;
        __syncthreads();
        {
            float s = attn_b[n0 + tid];
#pragma unroll
            for (int p = 0; p < HP_SPLITS; ++p)
                s += g_hproj_p[p][(size_t)b_idx * HDIM + n0 + tid];
            base_sh[tid] = s;
        }
        v_sh[tid] = v_w[n0 + tid];
        float acc[4][8][4] = {};
        gemm_mainloop1(g_eo_hi + (size_t)row0 * KEO, KEO,
                       g_w_hi + (size_t)n0 * KEO, KEO,
                       64, sm0, tid, acc);
#pragma unroll
        for (int mt = 0; mt < 4; ++mt)
#pragma unroll
            for (int nt = 0; nt < 8; ++nt) {
                int nb = wn * 64 + nt * 8 + (lane & 3) * 2;
                float b0 = base_sh[nb], b1 = base_sh[nb + 1];
                float v0 = v_sh[nb], v1 = v_sh[nb + 1];
                rowpart[mt][0] += v0 * ftanh(acc[mt][nt][0] + b0)
                                + v1 * ftanh(acc[mt][nt][1] + b1);
                rowpart[mt][1] += v0 * ftanh(acc[mt][nt][2] + b0)
                                + v1 * ftanh(acc[mt][nt][3] + b1);
            }
    }
#pragma unroll
    for (int mt = 0; mt < 4; ++mt)
#pragma unroll
        for (int h = 0; h < 2; ++h) {
            float v = rowpart[mt][h];
            v += __shfl_xor_sync(0xffffffff, v, 1);
            v += __shfl_xor_sync(0xffffffff, v, 2);
            if ((lane & 3) == 0)
                red[wn][wm * 64 + mt * 16 + (lane >> 2) + 8 * h] = v;
        }
    __syncthreads();
    if (tid < 128)
        g_score[row0 + tid] = red[0][tid] + red[1][tid] + red[2][tid] + red[3][tid];
}

// ================= fc: 1-term, B (fco_w) fp32->fp16 in-kernel, 3-stage =======
__device__ __forceinline__ void ldg_fcB(const float* __restrict__ fco,
                                        int n0, int kof, int tid, float4* r) {
    const float4* src = (const float4*)(fco + (size_t)(n0 + tid) * KCAT + kof);
#pragma unroll
    for (int j = 0; j < 8; ++j) r[j] = src[j];
}

__device__ __forceinline__ void sts_fcB(uint32_t sbase, int tid,
                                        const float4* r) {
    uint32_t bh = sbase + SM_A1 + tid * PADROW;
#pragma unroll
    for (int j = 0; j < 8; j += 2) {
        __half2 h0 = __floats2half2_rn(r[j].x,     r[j].y);
        __half2 h1 = __floats2half2_rn(r[j].z,     r[j].w);
        __half2 h2 = __floats2half2_rn(r[j + 1].x, r[j + 1].y);
        __half2 h3 = __floats2half2_rn(r[j + 1].z, r[j + 1].w);
        sts128(bh + j * 8, h2u(h0), h2u(h1), h2u(h2), h2u(h3));
    }
}

__device__ __forceinline__ void cp_fcA(uint32_t sbase, int kof, int tid) {
#pragma unroll
    for (int i = 0; i < 2; ++i) {
        int idx = tid + 256 * i;
        int r = idx >> 2, c = idx & 3;
        uint32_t d = sbase + r * PADROW + c * 16;
        size_t go = (size_t)r * KCAT + kof + c * 8;
        cp16(d, g_cat_hi + go);
    }
}

__global__ __launch_bounds__(256, 1)
void fc_mma(const float* __restrict__ fco_w, const float* __restrict__ fco_b,
            float* __restrict__ out) {
    extern __shared__ char dsm[];
    const uint32_t sm0 = smem_u32(dsm);
    const int tid = threadIdx.x, lane = tid & 31, wid = tid >> 5;
    const int wm = wid >> 2, wn = wid & 3;
    const int n0 = blockIdx.x * 256;
    const int KT = KCAT / 32;   // 112
    float acc[4][8][4] = {};
    float4 br[8];

    ldg_fcB(fco_w, n0, 0, tid, br);
    sts_fcB(sm0, tid, br);
    cp_fcA(sm0, 0, tid);
    CP_COMMIT();
    ldg_fcB(fco_w, n0, 32, tid, br);
    sts_fcB(sm0 + STAGE1, tid, br);
    cp_fcA(sm0 + STAGE1, 32, tid);
    CP_COMMIT();
    ldg_fcB(fco_w, n0, 64, tid, br);

    for (int it = 0; it < KT; ++it) {
        CP_WAIT(1);
        __syncthreads();
        const int s2 = (it + 2) % 3;
        if (it + 2 < KT) {
            sts_fcB(sm0 + s2 * STAGE1, tid, br);
            cp_fcA(sm0 + s2 * STAGE1, (it + 2) * 32, tid);
        }
        CP_COMMIT();
        if (it + 3 < KT) ldg_fcB(fco_w, n0, (it + 3) * 32, tid, br);
        stage_compute1(sm0 + (it % 3) * STAGE1, lane, wm, wn, acc);
    }
#pragma unroll
    for (int mt = 0; mt < 4; ++mt) {
        int r0 = wm * 64 + mt * 16 + (lane >> 2);
#pragma unroll
        for (int nt = 0; nt < 8; ++nt) {
            int n = n0 + wn * 64 + nt * 8 + (lane & 3) * 2;
            float b0 = fco_b[n], b1 = fco_b[n + 1];
            out[(size_t)r0 * VDIM + n] = acc[mt][nt][0] + b0;
            out[(size_t)r0 * VDIM + n + 1] = acc[mt][nt][1] + b1;
            out[(size_t)(r0 + 8) * VDIM + n] = acc[mt][nt][2] + b0;
            out[(size_t)(r0 + 8) * VDIM + n + 1] = acc[mt][nt][3] + b1;
        }
    }
}

// ================= gates: [x|h] @ [w_ih|w_hh]^T, split-K=8, 1-term ===========
__global__ __launch_bounds__(256, 1)
void gates_mma() {
    extern __shared__ char dsm[];
    const uint32_t sm0 = smem_u32(dsm);
    const int tid = threadIdx.x, lane = tid & 31, wid = tid >> 5;
    const int wm = wid >> 2, wn = wid & 3;
    const int n0 = (blockIdx.x & 15) * 256;
    const int ks = blockIdx.x >> 4;
    const int kof = ks * (KCAT / GT_SPLITS);
    float acc[4][8][4] = {};
    gemm_mainloop1(g_xh_hi + kof, KCAT,
                   g_wg_hi + (size_t)n0 * KCAT + kof, KCAT,
                   KCAT / GT_SPLITS / 32, sm0, tid, acc);
    float* gp = g_gatesp[ks];
#pragma unroll
    for (int mt = 0; mt < 4; ++mt) {
        int r0 = wm * 64 + mt * 16 + (lane >> 2);
#pragma unroll
        for (int nt = 0; nt < 8; ++nt) {
            int n = n0 + wn * 64 + nt * 8 + (lane & 3) * 2;
            gp[(size_t)r0 * NG + n] = acc[mt][nt][0];
            gp[(size_t)r0 * NG + n + 1] = acc[mt][nt][1];
            gp[(size_t)(r0 + 8) * NG + n] = acc[mt][nt][2];
            gp[(size_t)(r0 + 8) * NG + n + 1] = acc[mt][nt][3];
        }
    }
}

// ---------------- softmax over seq -------------------------------------------
__global__ void softmax_kernel() {
    __shared__ float sred[SLEN];
    int b = blockIdx.x, s = threadIdx.x;
    float sc = g_score[b * SLEN + s];
    sred[s] = sc; __syncthreads();
    for (int o = SLEN / 2; o > 0; o >>= 1) {
        if (s < o) sred[s] = fmaxf(sred[s], sred[s + o]);
        __syncthreads();
    }
    float m = sred[0]; __syncthreads();
    float e = expf(sc - m);
    sred[s] = e; __syncthreads();
    for (int o = SLEN / 2; o > 0; o >>= 1) {
        if (s < o) sred[s] += sred[s + o];
        __syncthreads();
    }
    g_attn[b * SLEN + s] = e / sred[0];
}

// ---------------- weighted = a @ eo (fp16 eo_hi, 4 cols/thread) --------------
__global__ void weighted_kernel() {
    __shared__ float a_sh[SLEN];
    int b = blockIdx.y;
    int d0 = (blockIdx.x * 256 + threadIdx.x) * 4;
    if (threadIdx.x < SLEN) a_sh[threadIdx.x] = g_attn[b * SLEN + threadIdx.x];
    __syncthreads();
    const __half* eob = g_eo_hi + (size_t)b * SLEN * KEO + d0;
    float acc0 = 0.f, acc1 = 0.f, acc2 = 0.f, acc3 = 0.f;
#pragma unroll 4
    for (int s = 0; s < SLEN; ++s) {
        uint2 u = *(const uint2*)(eob + (size_t)s * KEO);
        float2 p0 = __half22float2(*(__half2*)&u.x);
        float2 p1 = __half22float2(*(__half2*)&u.y);
        float a = a_sh[s];
        acc0 = fmaf(a, p0.x, acc0);
        acc1 = fmaf(a, p0.y, acc1);
        acc2 = fmaf(a, p1.x, acc2);
        acc3 = fmaf(a, p1.y, acc3);
    }
    float* gx = g_x + (size_t)b * KX + EDIM + d0;
    float* gc = g_cat + (size_t)b * KCAT + HDIM + d0;
    gx[0] = acc0; gx[1] = acc1; gx[2] = acc2; gx[3] = acc3;
    gc[0] = acc0; gc[1] = acc1; gc[2] = acc2; gc[3] = acc3;
}

// ---------------- LSTM cell elementwise --------------------------------------
__global__ void lstm_kernel(const float* __restrict__ c0,
                            const float* __restrict__ b_ih,
                            const float* __restrict__ b_hh,
                            float* __restrict__ out) {
    int idx = blockIdx.x * blockDim.x + threadIdx.x;   // [0, 128*1024)
    int b = idx >> 10, h = idx & 1023;
    float gs[4];
#pragma unroll
    for (int g = 0; g < 4; ++g) {
        float s = b_ih[g * HDIM + h] + b_hh[g * HDIM + h];
#pragma unroll
        for (int p = 0; p < GT_SPLITS; ++p)
            s += g_gatesp[p][(size_t)b * NG + g * HDIM + h];
        gs[g] = s;
    }
    float si = 1.f / (1.f + expf(-gs[0]));
    float sf = 1.f / (1.f + expf(-gs[1]));
    float so = 1.f / (1.f + expf(-gs[3]));
    float cn = sf * c0[idx] + si * tanhf(gs[2]);
    float hn = so * tanhf(cn);
    g_cat[(size_t)b * KCAT + h] = hn;
    out[(size_t)BS * VDIM + idx] = hn;                  // h_new
    out[(size_t)BS * VDIM + BS * HDIM + idx] = cn;      // c_new
}

// ---------------- launch -----------------------------------------------------
extern "C" void kernel_launch(void* const* d_in, const int* in_sizes, int n_in,
                              void* d_out, int out_size) {
    const int*   inp_tok = (const int*)  d_in[0];
    const float* h0      = (const float*)d_in[1];
    const float* c0      = (const float*)d_in[2];
    const float* eo      = (const float*)d_in[3];
    const float* emb_w   = (const float*)d_in[4];
    const float* attn_w  = (const float*)d_in[5];
    const float* attn_b  = (const float*)d_in[6];
    const float* v_w     = (const float*)d_in[7];
    const float* w_ih    = (const float*)d_in[8];
    const float* w_hh    = (const float*)d_in[9];
    const float* b_ih    = (const float*)d_in[10];
    const float* b_hh    = (const float*)d_in[11];
    const float* fco_w   = (const float*)d_in[12];
    const float* fco_b   = (const float*)d_in[13];
    float* out = (float*)d_out;

    void *p_eo_hi, *p_cat, *p_cat_hi;
    cudaGetSymbolAddress(&p_eo_hi,  g_eo_hi);
    cudaGetSymbolAddress(&p_cat,    g_cat);
    cudaGetSymbolAddress(&p_cat_hi, g_cat_hi);

    cudaFuncSetAttribute(attn_mma,  cudaFuncAttributeMaxDynamicSharedMemorySize, DSMEM1);
    cudaFuncSetAttribute(gates_mma, cudaFuncAttributeMaxDynamicSharedMemorySize, DSMEM1);
    cudaFuncSetAttribute(fc_mma,    cudaFuncAttributeMaxDynamicSharedMemorySize, DSMEM1);

    // conversions
    conv_hi<<<(ROWS * (size_t)KEO) / 4 / 256, 256>>>(
        (const float4*)eo, (__half2*)p_eo_hi);
    conv_w_kernel<<<HDIM, 256>>>(attn_w);
    conv_wg_kernel<<<NG, 256>>>(w_ih, w_hh);

    // embedding + h_proj (split-K x8)
    embed_kernel<<<BS, 256>>>(inp_tok, emb_w);
    hproj_splitk<<<dim3(HDIM / TBN, HP_SPLITS), NTHREADS>>>(h0, attn_w);

    // attention scores (fp32-acc GEMM + tanh + v-dot; sums hproj planes)
    attn_mma<<<256, 256, DSMEM1>>>(attn_b, v_w);
    softmax_kernel<<<BS, SLEN>>>();
    weighted_kernel<<<dim3(KEO / 1024, BS), 256>>>();

    // LSTM gates (split-K x8, 1-term)
    conv_xh_kernel<<<BS, 256>>>(h0);
    gates_mma<<<16 * GT_SPLITS, 256, DSMEM1>>>();
    lstm_kernel<<<(BS * HDIM) / 256, 256>>>(c0, b_ih, b_hh, out);

    // output projection (in-kernel fco conversion, 1-term, 3-stage)
    conv_hi<<<((size_t)BS * KCAT) / 4 / 256, 256>>>(
        (const float4*)p_cat, (__half2*)p_cat_hi);
    fc_mma<<<VDIM / 256, 256, DSMEM1>>>(fco_w, fco_b, out);
}